// round 4
// baseline (speedup 1.0000x reference)
#include <cuda_runtime.h>

#define C 8
#define G 2048      // gen rows per class
#define T 4096      // targets per class (gen + pos)
#define D 64
#define NTOT (C*G)  // 16384

// ---------------- scratch (device globals: allocation-free contract) -------
__device__ float g_K[(size_t)C * G * T];   // 256 MB kernel matrix
__device__ float g_sqg[NTOT];
__device__ float g_sqp[NTOT];
__device__ float g_rr[C * G];              // rsqrt(row sums)
__device__ float g_colsum[C * T];
__device__ float g_rc[C * T];              // rsqrt(col sums)
__device__ float g_acc[2];                 // loss sum, drift sum

// ---------------- init ------------------------------------------------------
__global__ void k_init() {
    int i = blockIdx.x * 256 + threadIdx.x;
    if (i < C * T) g_colsum[i] = 0.f;
    if (i < 2)     g_acc[i]    = 0.f;
}

// ---------------- squared norms --------------------------------------------
__global__ void k_sqnorm(const float* __restrict__ gen, const float* __restrict__ pos) {
    int r = blockIdx.x * 256 + threadIdx.x;
    if (r >= 2 * NTOT) return;
    const float* src = (r < NTOT) ? gen + (size_t)r * D : pos + (size_t)(r - NTOT) * D;
    const float4* p = (const float4*)src;
    float s = 0.f;
#pragma unroll
    for (int q = 0; q < 16; q++) {
        float4 v = p[q];
        s += v.x * v.x + v.y * v.y + v.z * v.z + v.w * v.w;
    }
    if (r < NTOT) g_sqg[r] = s; else g_sqp[r - NTOT] = s;
}

// ---------------- pass 1: K = exp(-20 * dist) -------------------------------
// block 256 = 16x16 threads, 64x64 tile, 4x4 micro-tile
__global__ void __launch_bounds__(256) k_pass1(const float* __restrict__ gen,
                                               const float* __restrict__ pos) {
    int cls = blockIdx.z;
    int i0 = blockIdx.y * 64;
    int j0 = blockIdx.x * 64;
    const float* genC = gen + (size_t)cls * G * D;
    const float* posC = pos + (size_t)cls * G * D;

    __shared__ __align__(16) float As[64][68];   // k-major: As[d][row]
    __shared__ __align__(16) float Bs[64][68];
    __shared__ float qs[64], tss[64];

    int t = threadIdx.x;
    int tx = t & 15, ty = t >> 4;

#pragma unroll
    for (int l = 0; l < 4; l++) {
        int idx4 = t + 256 * l;
        int row = idx4 >> 4;
        int d4 = (idx4 & 15) << 2;
        float4 v = *(const float4*)(genC + (size_t)(i0 + row) * D + d4);
        As[d4 + 0][row] = v.x; As[d4 + 1][row] = v.y;
        As[d4 + 2][row] = v.z; As[d4 + 3][row] = v.w;
        int jg = j0 + row;
        const float* src = (jg < G) ? (genC + (size_t)jg * D)
                                    : (posC + (size_t)(jg - G) * D);
        float4 w = *(const float4*)(src + d4);
        Bs[d4 + 0][row] = w.x; Bs[d4 + 1][row] = w.y;
        Bs[d4 + 2][row] = w.z; Bs[d4 + 3][row] = w.w;
    }
    if (t < 64) {
        qs[t] = g_sqg[cls * G + i0 + t];
    } else if (t < 128) {
        int jg = j0 + (t - 64);
        tss[t - 64] = (jg < G) ? g_sqg[cls * G + jg] : g_sqp[cls * G + jg - G];
    }
    __syncthreads();

    float acc[4][4] = {};
#pragma unroll 16
    for (int k = 0; k < 64; k++) {
        float4 a = *(const float4*)&As[k][ty * 4];
        float4 b = *(const float4*)&Bs[k][tx * 4];
        acc[0][0] += a.x * b.x; acc[0][1] += a.x * b.y; acc[0][2] += a.x * b.z; acc[0][3] += a.x * b.w;
        acc[1][0] += a.y * b.x; acc[1][1] += a.y * b.y; acc[1][2] += a.y * b.z; acc[1][3] += a.y * b.w;
        acc[2][0] += a.z * b.x; acc[2][1] += a.z * b.y; acc[2][2] += a.z * b.z; acc[2][3] += a.z * b.w;
        acc[3][0] += a.w * b.x; acc[3][1] += a.w * b.y; acc[3][2] += a.w * b.z; acc[3][3] += a.w * b.w;
    }

    float* Kc = g_K + (size_t)cls * G * T;
#pragma unroll
    for (int ri = 0; ri < 4; ri++) {
        int i = ty * 4 + ri;
        int gi = i0 + i;
        float q = qs[i];
        float o[4];
#pragma unroll
        for (int rj = 0; rj < 4; rj++) {
            int j = tx * 4 + rj;
            int gj = j0 + j;
            float d2 = q + tss[j] - 2.f * acc[ri][rj];
            float dist = sqrtf(fmaxf(d2, 0.f)) * 0.125f;    // /sqrt(64)
            // diag of gen block -> dist=1e6 -> exp underflows to exactly 0
            o[rj] = (gj == gi) ? 0.f : __expf(-20.f * dist);
        }
        float4 ov = make_float4(o[0], o[1], o[2], o[3]);
        *(float4*)(Kc + (size_t)gi * T + j0 + tx * 4) = ov;
    }
}

// ---------------- row sums -> rr -------------------------------------------
__global__ void k_rowsum() {
    int row = blockIdx.x;                       // 0..C*G-1
    const float4* p = (const float4*)(g_K + (size_t)row * T);
    int t = threadIdx.x;                        // 128 threads
    float s = 0.f;
#pragma unroll
    for (int q = 0; q < 8; q++) {
        float4 v = p[t + 128 * q];
        s += (v.x + v.y) + (v.z + v.w);
    }
#pragma unroll
    for (int off = 16; off > 0; off >>= 1) s += __shfl_down_sync(0xffffffffu, s, off);
    __shared__ float ws[4];
    if ((t & 31) == 0) ws[t >> 5] = s;
    __syncthreads();
    if (t == 0) g_rr[row] = rsqrtf(ws[0] + ws[1] + ws[2] + ws[3]);
}

// ---------------- col sums (partial, atomics) -------------------------------
__global__ void k_colsum() {
    int cls = blockIdx.z;
    int j = blockIdx.x * 256 + threadIdx.x;
    int i0 = blockIdx.y * 256;
    const float* base = g_K + (size_t)cls * G * T + (size_t)i0 * T + j;
    float s = 0.f;
#pragma unroll 8
    for (int i = 0; i < 256; i++) s += base[(size_t)i * T];
    atomicAdd(&g_colsum[cls * T + j], s);
}

__global__ void k_rc() {
    int i = blockIdx.x * 256 + threadIdx.x;
    if (i < C * T) g_rc[i] = rsqrtf(g_colsum[i]);
}

// ---------------- pass 2: weighted GEMM + V + reductions --------------------
// block 256 = 16x16 threads, 32 rows/block, micro 2 rows x 4 dims, j tiles of 64
__global__ void __launch_bounds__(256) k_pass2(const float* __restrict__ gen,
                                               const float* __restrict__ pos) {
    int cls = blockIdx.y;
    int i0 = blockIdx.x * 32;
    const float* genC = gen + (size_t)cls * G * D;
    const float* posC = pos + (size_t)cls * G * D;
    const float* Kcls = g_K + (size_t)cls * G * T;

    __shared__ __align__(16) float ws_s[64][34];   // [j][row]
    __shared__ __align__(16) float ts_s[64][64];   // [j][d]
    __shared__ float rrs[32];
    __shared__ float sgS[32], spS[32];
    __shared__ float blk[2][16];

    int t = threadIdx.x;
    int tx = t & 15, ty = t >> 4;
    if (t < 32) rrs[t] = g_rr[cls * G + i0 + t];

    float accN[2][4] = {}, accP[2][4] = {};
    float sN[2] = {0.f, 0.f}, sP[2] = {0.f, 0.f};

    for (int jt = 0; jt < 64; jt++) {
        int jg0 = jt * 64;
        __syncthreads();
        // target tile
#pragma unroll
        for (int l = 0; l < 4; l++) {
            int idx4 = t + 256 * l;
            int jr = idx4 >> 4;
            int d4 = (idx4 & 15) << 2;
            int jg = jg0 + jr;
            const float* src = (jg < G) ? (genC + (size_t)jg * D)
                                        : (posC + (size_t)(jg - G) * D);
            *(float4*)&ts_s[jr][d4] = *(const float4*)(src + d4);
        }
        // K tile -> w tile (min(rr*rc,1e6)*K), plus per-row partial sums
        int jb = cls * T + jg0 + tx * 4;
        float rc0 = g_rc[jb + 0], rc1 = g_rc[jb + 1];
        float rc2 = g_rc[jb + 2], rc3 = g_rc[jb + 3];
        float sl0 = 0.f, sl1 = 0.f;
#pragma unroll
        for (int r = 0; r < 2; r++) {
            int row = ty * 2 + r;
            float rrv = rrs[row];
            float4 kv = *(const float4*)(Kcls + (size_t)(i0 + row) * T + jg0 + tx * 4);
            float w0 = fminf(rrv * rc0, 1e6f) * kv.x;
            float w1 = fminf(rrv * rc1, 1e6f) * kv.y;
            float w2 = fminf(rrv * rc2, 1e6f) * kv.z;
            float w3 = fminf(rrv * rc3, 1e6f) * kv.w;
            ws_s[tx * 4 + 0][row] = w0; ws_s[tx * 4 + 1][row] = w1;
            ws_s[tx * 4 + 2][row] = w2; ws_s[tx * 4 + 3][row] = w3;
            float ss = (w0 + w1) + (w2 + w3);
            if (r == 0) sl0 = ss; else sl1 = ss;
        }
        __syncthreads();

        if (jg0 < G) {
            sN[0] += sl0; sN[1] += sl1;
#pragma unroll 16
            for (int j = 0; j < 64; j++) {
                float2 a = *(const float2*)&ws_s[j][ty * 2];
                float4 b = *(const float4*)&ts_s[j][tx * 4];
                accN[0][0] += a.x * b.x; accN[0][1] += a.x * b.y;
                accN[0][2] += a.x * b.z; accN[0][3] += a.x * b.w;
                accN[1][0] += a.y * b.x; accN[1][1] += a.y * b.y;
                accN[1][2] += a.y * b.z; accN[1][3] += a.y * b.w;
            }
        } else {
            sP[0] += sl0; sP[1] += sl1;
#pragma unroll 16
            for (int j = 0; j < 64; j++) {
                float2 a = *(const float2*)&ws_s[j][ty * 2];
                float4 b = *(const float4*)&ts_s[j][tx * 4];
                accP[0][0] += a.x * b.x; accP[0][1] += a.x * b.y;
                accP[0][2] += a.x * b.z; accP[0][3] += a.x * b.w;
                accP[1][0] += a.y * b.x; accP[1][1] += a.y * b.y;
                accP[1][2] += a.y * b.z; accP[1][3] += a.y * b.w;
            }
        }
    }

    // reduce S over tx (16-lane segments)
#pragma unroll
    for (int off = 8; off > 0; off >>= 1) {
        sN[0] += __shfl_down_sync(0xffffffffu, sN[0], off, 16);
        sN[1] += __shfl_down_sync(0xffffffffu, sN[1], off, 16);
        sP[0] += __shfl_down_sync(0xffffffffu, sP[0], off, 16);
        sP[1] += __shfl_down_sync(0xffffffffu, sP[1], off, 16);
    }
    if (tx == 0) {
        sgS[ty * 2 + 0] = sN[0]; sgS[ty * 2 + 1] = sN[1];
        spS[ty * 2 + 0] = sP[0]; spS[ty * 2 + 1] = sP[1];
    }
    __syncthreads();

    // V = S_g * accP - S_p * accN ; reduce loss and per-row norms
    float lossp = 0.f;
    float rv2[2] = {0.f, 0.f};
#pragma unroll
    for (int r = 0; r < 2; r++) {
        float sg = sgS[ty * 2 + r], sp = spS[ty * 2 + r];
#pragma unroll
        for (int q = 0; q < 4; q++) {
            float v = sg * accP[r][q] - sp * accN[r][q];
            lossp += v * v;
            rv2[r] += v * v;
        }
    }
#pragma unroll
    for (int off = 8; off > 0; off >>= 1) {
        lossp  += __shfl_down_sync(0xffffffffu, lossp,  off, 16);
        rv2[0] += __shfl_down_sync(0xffffffffu, rv2[0], off, 16);
        rv2[1] += __shfl_down_sync(0xffffffffu, rv2[1], off, 16);
    }
    if (tx == 0) {
        blk[0][ty] = lossp;
        blk[1][ty] = sqrtf(rv2[0]) + sqrtf(rv2[1]);
    }
    __syncthreads();
    if (t == 0) {
        float L = 0.f, Dr = 0.f;
#pragma unroll
        for (int q = 0; q < 16; q++) { L += blk[0][q]; Dr += blk[1][q]; }
        atomicAdd(&g_acc[0], L);
        atomicAdd(&g_acc[1], Dr);
    }
}

// ---------------- finalize ---------------------------------------------------
__global__ void k_final(float* __restrict__ out, int out_size) {
    int i = threadIdx.x;
    if (i >= out_size) return;
    float v = 0.f;
    if (i == 0) v = g_acc[0] / (float)((size_t)NTOT * D);
    else if (i == 1) v = g_acc[1] / (float)NTOT;
    out[i] = v;
}

// ---------------- launch -----------------------------------------------------
extern "C" void kernel_launch(void* const* d_in, const int* in_sizes, int n_in,
                              void* d_out, int out_size) {
    (void)in_sizes; (void)n_in;
    const float* gen = (const float*)d_in[0];   // generated [16384,64]
    const float* pos = (const float*)d_in[2];   // positive  [16384,64]
    float* out = (float*)d_out;

    k_init<<<(C * T + 255) / 256, 256>>>();
    k_sqnorm<<<(2 * NTOT + 255) / 256, 256>>>(gen, pos);
    k_pass1<<<dim3(T / 64, G / 64, C), 256>>>(gen, pos);
    k_rowsum<<<C * G, 128>>>();
    k_colsum<<<dim3(T / 256, G / 256, C), 256>>>();
    k_rc<<<(C * T + 255) / 256, 256>>>();
    k_pass2<<<dim3(G / 32, C), 256>>>(gen, pos);
    k_final<<<1, 32>>>(out, out_size);
}